// round 8
// baseline (speedup 1.0000x reference)
#include <cuda_runtime.h>
#include <cuda_bf16.h>
#include <math_constants.h>
#include <cstdint>

#define BB   16
#define T1C  512
#define T2C  64
#define DC   768
#define HC   12
#define EC   64
#define TKC  576
#define SCALE_P 0.3535533905932738f

// ---------------- scratch ----------------
__device__ float    g_projF[6ULL * BB * T1C * DC];   // tf32-bit floats
__device__ float    g_projI[6ULL * BB * T2C * DC];
__device__ float    g_attV [(size_t)BB * T1C * DC];  // plain fp32
__device__ float    g_attL [(size_t)BB * T2C * DC];
__device__ float    g_maskF[BB * TKC];
__device__ unsigned g_featsT[(size_t)BB * T1C * DC]; // tf32 bits, k-pair permuted
__device__ unsigned g_inpsT [(size_t)BB * T2C * DC];
__device__ unsigned g_attVT [(size_t)BB * T1C * DC];
__device__ unsigned g_attLT [(size_t)BB * T2C * DC];
__device__ unsigned g_WfT[6ULL * DC * DC];           // [z][n][k] tf32 bits, permuted
__device__ unsigned g_WiT[6ULL * DC * DC];
__device__ unsigned g_WuvT[(size_t)DC * DC];
__device__ unsigned g_WulT[(size_t)DC * DC];

__device__ __forceinline__ unsigned f2tf32(float x)
{ unsigned u; asm("cvt.rna.tf32.f32 %0, %1;" : "=r"(u) : "f"(x)); return u; }

#define MMA_TF32(d, a0, a1, a2, a3, b0, b1)                                   \
    asm volatile("mma.sync.aligned.m16n8k8.row.col.f32.tf32.tf32.f32 "        \
                 "{%0,%1,%2,%3}, {%4,%5,%6,%7}, {%8,%9}, {%0,%1,%2,%3};\n"    \
                 : "+f"(d[0]), "+f"(d[1]), "+f"(d[2]), "+f"(d[3])             \
                 : "r"(a0), "r"(a1), "r"(a2), "r"(a3), "r"(b0), "r"(b1))

__device__ __forceinline__ void cp16(void* dst, const void* src)
{
    unsigned sa = (unsigned)__cvta_generic_to_shared(dst);
    asm volatile("cp.async.ca.shared.global [%0], [%1], 16;" :: "r"(sa), "l"(src));
}
#define CP_COMMIT() asm volatile("cp.async.commit_group;")
template <int N>
__device__ __forceinline__ void cp_wait() { asm volatile("cp.async.wait_group %0;" :: "n"(N)); }

// ---------------- mask prep ----------------
__global__ void mask_prep_kernel(const unsigned* __restrict__ raw, float* __restrict__ mf)
{
    __shared__ int flags[2];
    int tid = threadIdx.x;
    if (tid < 2) flags[tid] = 0;
    __syncthreads();
    int notInt = 0, notU8 = 0;
    const int nWords = (BB * TKC) / 4;
    for (int i = tid; i < nWords; i += blockDim.x) {
        unsigned w = raw[i];
        if (w > 1u) notInt = 1;
        if (w & 0xFEFEFEFEu) notU8 = 1;
    }
    if (notInt) atomicOr(&flags[0], 1);
    if (notU8)  atomicOr(&flags[1], 1);
    __syncthreads();
    int mode = !flags[0] ? 0 : (!flags[1] ? 1 : 2);
    for (int i = tid; i < BB * TKC; i += blockDim.x) {
        float v;
        if (mode == 0)      v = ((const int*)raw)[i] ? 1.f : 0.f;
        else if (mode == 1) v = ((const unsigned char*)raw)[i] ? 1.f : 0.f;
        else                v = (((const float*)raw)[i] != 0.f) ? 1.f : 0.f;
        mf[i] = v;
    }
}

// ---------------- fp32 -> tf32 bits with k-pair permutation ----------------
// Each 8-k group is reordered to [k0,k4,k1,k5,k2,k6,k3,k7] so a v2 load at
// position 2*tg yields the (k, k+4) tf32 fragment pair.
__global__ void cvt_perm_kernel(const float* __restrict__ src, unsigned* __restrict__ dst, int M)
{
    int total = M * 96;
    for (int i = blockIdx.x * blockDim.x + threadIdx.x; i < total; i += gridDim.x * blockDim.x) {
        int m = i / 96, kq = i % 96;
        const float* s = src + (size_t)m * DC + kq * 8;
        float4 v0 = *(const float4*)s, v1 = *(const float4*)(s + 4);
        uint4 u0, u1;
        u0.x = f2tf32(v0.x); u0.y = f2tf32(v1.x); u0.z = f2tf32(v0.y); u0.w = f2tf32(v1.y);
        u1.x = f2tf32(v0.z); u1.y = f2tf32(v1.z); u1.z = f2tf32(v0.w); u1.w = f2tf32(v1.w);
        uint4* d = (uint4*)(dst + (size_t)m * DC + kq * 8);
        d[0] = u0; d[1] = u1;
    }
}

// ---------------- W[z][k][n] -> WT[z][n][k] tf32 bits, k-pair permuted ----------------
__global__ void wtrans_perm_kernel(const float* __restrict__ W, unsigned* __restrict__ WT)
{
    __shared__ float tile[64][65];
    int tid = threadIdx.x;
    int n0 = blockIdx.x * 64, k0 = blockIdx.y * 64;
    const float* Wz = W + (size_t)blockIdx.z * DC * DC;
    unsigned* Dz = WT + (size_t)blockIdx.z * DC * DC;

    for (int i = tid; i < 4096; i += 256) {
        int r = i >> 6, c = i & 63;
        tile[r][c] = Wz[(size_t)(k0 + r) * DC + n0 + c];
    }
    __syncthreads();
#pragma unroll
    for (int it = 0; it < 2; it++) {
        int idx = tid + it * 256;        // 0..511
        int n = idx >> 3, kq = idx & 7;  // one 8-k group per item
        float x[8];
#pragma unroll
        for (int j = 0; j < 8; j++) x[j] = tile[kq * 8 + j][n];
        uint4 u0, u1;
        u0.x = f2tf32(x[0]); u0.y = f2tf32(x[4]); u0.z = f2tf32(x[1]); u0.w = f2tf32(x[5]);
        u1.x = f2tf32(x[2]); u1.y = f2tf32(x[6]); u1.z = f2tf32(x[3]); u1.w = f2tf32(x[7]);
        uint4* d = (uint4*)(Dz + (size_t)(n0 + n) * DC + k0 + kq * 8);
        d[0] = u0; d[1] = u1;
    }
}

// ---------------- tf32 GEMM, 64x64 warp tiles ----------------
// C[z][m][n] = (A[m][:] . WT[z][n][:] + bias[z][n]) * scale
// CTA: 128 threads / 4 warps, tile 128x128, chunk K=32, 2-stage cp.async.
#define PAD 40
#define STG_WORDS (2 * 128 * PAD)        // A + B per stage = 40960 B
#define GEMM_SMEM (2 * STG_WORDS * 4)    // 81920 B

__global__ __launch_bounds__(128, 2) void tf32gemm_kernel(
    const unsigned* __restrict__ A, const unsigned* __restrict__ Bt,
    const float* __restrict__ bias, float* __restrict__ C,
    int M, float scale, int outTf32)
{
    extern __shared__ unsigned sh[];
    const int tid  = threadIdx.x;
    const int wid  = tid >> 5;
    const int lane = tid & 31;
    const int g    = lane >> 2;
    const int tg   = lane & 3;
    const int warpM = (wid & 1) * 64;
    const int warpN = (wid >> 1) * 64;

    const size_t z = blockIdx.z;
    Bt   += z * (size_t)DC * DC;
    bias += z * (size_t)DC;
    C    += z * (size_t)M * DC;

    const int rowBase = blockIdx.y * 128;
    const int colBase = blockIdx.x * 128;

    const unsigned* Ag = A  + (size_t)(rowBase + tid) * DC;   // thread owns one A row
    const unsigned* Bg = Bt + (size_t)(colBase + tid) * DC;   // and one B(n) row

    float acc[4][8][4];
#pragma unroll
    for (int mt = 0; mt < 4; mt++)
#pragma unroll
        for (int nt = 0; nt < 8; nt++)
#pragma unroll
            for (int r = 0; r < 4; r++) acc[mt][nt][r] = 0.f;

    auto fill = [&](int b, int c) {
        unsigned* As = sh + b * STG_WORDS + tid * PAD;
        unsigned* Bs = sh + b * STG_WORDS + 128 * PAD + tid * PAD;
        const unsigned* As_g = Ag + c * 32;
        const unsigned* Bs_g = Bg + c * 32;
#pragma unroll
        for (int j = 0; j < 8; j++) cp16(As + j * 4, As_g + j * 4);
#pragma unroll
        for (int j = 0; j < 8; j++) cp16(Bs + j * 4, Bs_g + j * 4);
    };

    const int NC = DC / 32;   // 24
    fill(0, 0); CP_COMMIT();

    for (int c = 0; c < NC; c++) {
        int b = c & 1;
        if (c + 1 < NC) { fill(b ^ 1, c + 1); CP_COMMIT(); cp_wait<1>(); }
        else            { cp_wait<0>(); }
        __syncthreads();

        const unsigned* Ab = sh + b * STG_WORDS;
        const unsigned* Bb = Ab + 128 * PAD;
#pragma unroll
        for (int ks = 0; ks < 32; ks += 8) {
            uint2 av[4][2];
#pragma unroll
            for (int mt = 0; mt < 4; mt++) {
                int r0 = warpM + mt * 16 + g;
                av[mt][0] = *(const uint2*)&Ab[r0 * PAD + ks + 2 * tg];
                av[mt][1] = *(const uint2*)&Ab[(r0 + 8) * PAD + ks + 2 * tg];
            }
            uint2 bv[8];
#pragma unroll
            for (int nt = 0; nt < 8; nt++)
                bv[nt] = *(const uint2*)&Bb[(warpN + nt * 8 + g) * PAD + ks + 2 * tg];
#pragma unroll
            for (int mt = 0; mt < 4; mt++)
#pragma unroll
                for (int nt = 0; nt < 8; nt++)
                    MMA_TF32(acc[mt][nt], av[mt][0].x, av[mt][1].x, av[mt][0].y, av[mt][1].y,
                             bv[nt].x, bv[nt].y);
        }
        __syncthreads();
    }

    // epilogue
#pragma unroll
    for (int mt = 0; mt < 4; mt++) {
        int row0 = rowBase + warpM + mt * 16 + g;
#pragma unroll
        for (int nt = 0; nt < 8; nt++) {
            int col = colBase + warpN + nt * 8 + 2 * tg;
            float b0 = bias[col], b1 = bias[col + 1];
            float v0 = (acc[mt][nt][0] + b0) * scale;
            float v1 = (acc[mt][nt][1] + b1) * scale;
            float v2 = (acc[mt][nt][2] + b0) * scale;
            float v3 = (acc[mt][nt][3] + b1) * scale;
            if (outTf32) {
                v0 = __uint_as_float(f2tf32(v0));
                v1 = __uint_as_float(f2tf32(v1));
                v2 = __uint_as_float(f2tf32(v2));
                v3 = __uint_as_float(f2tf32(v3));
            }
            *(float2*)(C + (size_t)row0 * DC + col)       = make_float2(v0, v1);
            *(float2*)(C + (size_t)(row0 + 8) * DC + col) = make_float2(v2, v3);
        }
    }
}

// ---------------- mma-based flash attention (tf32 in, fp32 out) ----------------
#define APAD 68
#define VPAD 72

__global__ __launch_bounds__(128) void attn_mma_kernel(
    const float* __restrict__ Qa, const float* __restrict__ Qb,
    const float* __restrict__ Kf, const float* __restrict__ Ki,
    const float* __restrict__ Vf, const float* __restrict__ Vi,
    const float* __restrict__ maskF, float* __restrict__ Out, int Tq)
{
    extern __shared__ unsigned smu[];
    unsigned* Qs = smu;
    unsigned* Ks = Qs + 64 * APAD;
    unsigned* Vs = Ks + 64 * APAD;
    unsigned* Ps = Vs + 64 * VPAD;
    float*    Ms = (float*)(Ps + 64 * APAD);

    const int tid = threadIdx.x;
    const int wid = tid >> 5;
    const int g = (tid & 31) >> 2;
    const int tg = tid & 3;
    const int wr = wid * 16;

    const int qt = blockIdx.x, h = blockIdx.y, b = blockIdx.z;
    const int qBase = qt * 64;

    const float* Qa_p = Qa + ((size_t)b * Tq + qBase) * DC + h * EC;
    const float* Qb_p = Qb + ((size_t)b * Tq + qBase) * DC + h * EC;
    const float* Kf_p = Kf + (size_t)b * T1C * DC + h * EC;
    const float* Ki_p = Ki + (size_t)b * T2C * DC + h * EC;
    const float* Vf_p = Vf + (size_t)b * T1C * DC + h * EC;
    const float* Vi_p = Vi + (size_t)b * T2C * DC + h * EC;

    for (int i = tid; i < TKC; i += 128) Ms[i] = maskF[b * TKC + i];

    for (int i = tid; i < 64 * 16; i += 128) {
        int r = i >> 4, c = (i & 15) << 2;
        *(uint4*)&Qs[r * APAD + c] = *(const uint4*)(Qa_p + (size_t)r * DC + c);
    }

    float o[8][4];
#pragma unroll
    for (int et = 0; et < 8; et++)
#pragma unroll
        for (int r = 0; r < 4; r++) o[et][r] = 0.f;
    float mx0 = -CUDART_INF_F, mx1 = -CUDART_INF_F, l0 = 0.f, l1 = 0.f;

    for (int t = 0; t < 9; t++) {
        const float *Kp, *Vp;
        int keyBase;
        if (t < 8) { Kp = Kf_p + (size_t)t * 64 * DC; Vp = Vf_p + (size_t)t * 64 * DC; keyBase = t * 64; }
        else       { Kp = Ki_p;                       Vp = Vi_p;                       keyBase = T1C; }

        __syncthreads();
        if (t == 8) {
            for (int i = tid; i < 64 * 16; i += 128) {
                int r = i >> 4, c = (i & 15) << 2;
                *(uint4*)&Qs[r * APAD + c] = *(const uint4*)(Qb_p + (size_t)r * DC + c);
            }
        }
        for (int i = tid; i < 64 * 16; i += 128) {
            int r = i >> 4, c = (i & 15) << 2;
            *(uint4*)&Ks[r * APAD + c] = *(const uint4*)(Kp + (size_t)r * DC + c);
            *(uint4*)&Vs[r * VPAD + c] = *(const uint4*)(Vp + (size_t)r * DC + c);
        }
        __syncthreads();

        float s[8][4];
#pragma unroll
        for (int nt = 0; nt < 8; nt++)
#pragma unroll
            for (int r = 0; r < 4; r++) s[nt][r] = 0.f;

#pragma unroll
        for (int ks = 0; ks < 64; ks += 8) {
            unsigned a0 = Qs[(wr + g) * APAD + ks + tg];
            unsigned a1 = Qs[(wr + g + 8) * APAD + ks + tg];
            unsigned a2 = Qs[(wr + g) * APAD + ks + tg + 4];
            unsigned a3 = Qs[(wr + g + 8) * APAD + ks + tg + 4];
#pragma unroll
            for (int nt = 0; nt < 8; nt++) {
                unsigned b0 = Ks[(nt * 8 + g) * APAD + ks + tg];
                unsigned b1 = Ks[(nt * 8 + g) * APAD + ks + tg + 4];
                MMA_TF32(s[nt], a0, a1, a2, a3, b0, b1);
            }
        }

        float tm0 = -CUDART_INF_F, tm1 = -CUDART_INF_F;
#pragma unroll
        for (int nt = 0; nt < 8; nt++) {
            float mk0 = Ms[keyBase + nt * 8 + 2 * tg];
            float mk1 = Ms[keyBase + nt * 8 + 2 * tg + 1];
            if (mk0 != 0.f) { s[nt][0] = -1e9f; s[nt][2] = -1e9f; }
            if (mk1 != 0.f) { s[nt][1] = -1e9f; s[nt][3] = -1e9f; }
            tm0 = fmaxf(tm0, fmaxf(s[nt][0], s[nt][1]));
            tm1 = fmaxf(tm1, fmaxf(s[nt][2], s[nt][3]));
        }
        tm0 = fmaxf(tm0, __shfl_xor_sync(0xffffffffu, tm0, 1));
        tm0 = fmaxf(tm0, __shfl_xor_sync(0xffffffffu, tm0, 2));
        tm1 = fmaxf(tm1, __shfl_xor_sync(0xffffffffu, tm1, 1));
        tm1 = fmaxf(tm1, __shfl_xor_sync(0xffffffffu, tm1, 2));

        float mn0 = fmaxf(mx0, tm0), mn1 = fmaxf(mx1, tm1);
        float sc0 = __expf(mx0 - mn0), sc1 = __expf(mx1 - mn1);
        mx0 = mn0; mx1 = mn1;

        float rs0 = 0.f, rs1 = 0.f;
#pragma unroll
        for (int nt = 0; nt < 8; nt++) {
            s[nt][0] = __expf(s[nt][0] - mn0); rs0 += s[nt][0];
            s[nt][1] = __expf(s[nt][1] - mn0); rs0 += s[nt][1];
            s[nt][2] = __expf(s[nt][2] - mn1); rs1 += s[nt][2];
            s[nt][3] = __expf(s[nt][3] - mn1); rs1 += s[nt][3];
        }
        rs0 += __shfl_xor_sync(0xffffffffu, rs0, 1);
        rs0 += __shfl_xor_sync(0xffffffffu, rs0, 2);
        rs1 += __shfl_xor_sync(0xffffffffu, rs1, 1);
        rs1 += __shfl_xor_sync(0xffffffffu, rs1, 2);
        l0 = l0 * sc0 + rs0;
        l1 = l1 * sc1 + rs1;
#pragma unroll
        for (int et = 0; et < 8; et++) {
            o[et][0] *= sc0; o[et][1] *= sc0;
            o[et][2] *= sc1; o[et][3] *= sc1;
        }

#pragma unroll
        for (int nt = 0; nt < 8; nt++) {
            *(uint2*)&Ps[(wr + g) * APAD + nt * 8 + 2 * tg]     = make_uint2(f2tf32(s[nt][0]), f2tf32(s[nt][1]));
            *(uint2*)&Ps[(wr + g + 8) * APAD + nt * 8 + 2 * tg] = make_uint2(f2tf32(s[nt][2]), f2tf32(s[nt][3]));
        }
        __syncwarp();

#pragma unroll
        for (int ks = 0; ks < 64; ks += 8) {
            unsigned a0 = Ps[(wr + g) * APAD + ks + tg];
            unsigned a1 = Ps[(wr + g + 8) * APAD + ks + tg];
            unsigned a2 = Ps[(wr + g) * APAD + ks + tg + 4];
            unsigned a3 = Ps[(wr + g + 8) * APAD + ks + tg + 4];
#pragma unroll
            for (int et = 0; et < 8; et++) {
                unsigned b0 = Vs[(ks + tg) * VPAD + et * 8 + g];
                unsigned b1 = Vs[(ks + tg + 4) * VPAD + et * 8 + g];
                MMA_TF32(o[et], a0, a1, a2, a3, b0, b1);
            }
        }
    }

    float inv0 = 1.f / l0, inv1 = 1.f / l1;
    int r0 = qBase + wr + g;
#pragma unroll
    for (int et = 0; et < 8; et++) {
        int col = h * EC + et * 8 + 2 * tg;
        *(float2*)(Out + ((size_t)b * Tq + r0) * DC + col)     = make_float2(o[et][0] * inv0, o[et][1] * inv0);
        *(float2*)(Out + ((size_t)b * Tq + r0 + 8) * DC + col) = make_float2(o[et][2] * inv1, o[et][3] * inv1);
    }
}

// ---------------- launch ----------------
extern "C" void kernel_launch(void* const* d_in, const int* in_sizes, int n_in,
                              void* d_out, int out_size)
{
    const float* feats = (const float*)d_in[0];
    const float* inps  = (const float*)d_in[1];
    const void*  amask = d_in[2];
    const float* W_f   = (const float*)d_in[3];
    const float* b_f   = (const float*)d_in[4];
    const float* W_i   = (const float*)d_in[5];
    const float* b_i   = (const float*)d_in[6];
    const float* Wu_v  = (const float*)d_in[7];
    const float* bu_v  = (const float*)d_in[8];
    const float* Wu_l  = (const float*)d_in[9];
    const float* bu_l  = (const float*)d_in[10];
    float* out = (float*)d_out;

    float *projF, *projI, *attV, *attL, *maskF;
    unsigned *featsT, *inpsT, *attVT, *attLT, *WfT, *WiT, *WuvT, *WulT;
    cudaGetSymbolAddress((void**)&projF, g_projF);
    cudaGetSymbolAddress((void**)&projI, g_projI);
    cudaGetSymbolAddress((void**)&attV,  g_attV);
    cudaGetSymbolAddress((void**)&attL,  g_attL);
    cudaGetSymbolAddress((void**)&maskF, g_maskF);
    cudaGetSymbolAddress((void**)&featsT, g_featsT);
    cudaGetSymbolAddress((void**)&inpsT,  g_inpsT);
    cudaGetSymbolAddress((void**)&attVT,  g_attVT);
    cudaGetSymbolAddress((void**)&attLT,  g_attLT);
    cudaGetSymbolAddress((void**)&WfT,  g_WfT);
    cudaGetSymbolAddress((void**)&WiT,  g_WiT);
    cudaGetSymbolAddress((void**)&WuvT, g_WuvT);
    cudaGetSymbolAddress((void**)&WulT, g_WulT);

    const size_t SF = (size_t)BB * T1C * DC;
    const size_t SI = (size_t)BB * T2C * DC;
    const int M1 = BB * T1C, M2 = BB * T2C;

    const int attnSmem = (3 * 64 * APAD + 64 * VPAD + TKC) * (int)sizeof(unsigned);
    cudaFuncSetAttribute(tf32gemm_kernel, cudaFuncAttributeMaxDynamicSharedMemorySize, GEMM_SMEM);
    cudaFuncSetAttribute(attn_mma_kernel, cudaFuncAttributeMaxDynamicSharedMemorySize, attnSmem);

    // 1) prep: mask + permuted tf32 operands
    mask_prep_kernel<<<1, 256>>>((const unsigned*)amask, maskF);
    cvt_perm_kernel<<<1024, 256>>>(feats, featsT, M1);
    cvt_perm_kernel<<<256, 256>>>(inps, inpsT, M2);
    wtrans_perm_kernel<<<dim3(12, 12, 6), 256>>>(W_f, WfT);
    wtrans_perm_kernel<<<dim3(12, 12, 6), 256>>>(W_i, WiT);
    wtrans_perm_kernel<<<dim3(12, 12, 1), 256>>>(Wu_v, WuvT);
    wtrans_perm_kernel<<<dim3(12, 12, 1), 256>>>(Wu_l, WulT);

    // 2) projections (tf32-rounded out for attention)
    tf32gemm_kernel<<<dim3(6, M1 / 128, 6), 128, GEMM_SMEM>>>(featsT, WfT, b_f, projF, M1, SCALE_P, 1);
    tf32gemm_kernel<<<dim3(6, M2 / 128, 6), 128, GEMM_SMEM>>>(inpsT, WiT, b_i, projI, M2, SCALE_P, 1);

    // feats stack: [k_vv, q_vv, v_vv, q_lv, k_vl, v_vl]
    // inps  stack: [k_lv, v_lv, q_vl, q_ll, k_ll, v_ll]

    // 3) attention (fp32 out)
    attn_mma_kernel<<<dim3(T1C / 64, HC, BB), 128, attnSmem>>>(
        projF + 1 * SF, projF + 3 * SF,
        projF + 0 * SF, projI + 0 * SI,
        projF + 2 * SF, projI + 1 * SI,
        maskF, attV, T1C);
    attn_mma_kernel<<<dim3(T2C / 64, HC, BB), 128, attnSmem>>>(
        projI + 2 * SI, projI + 3 * SI,
        projF + 4 * SF, projI + 4 * SI,
        projF + 5 * SF, projI + 5 * SI,
        maskF, attL, T2C);

    // 4) permute attention outputs, then output projections into d_out
    cvt_perm_kernel<<<1024, 256>>>(attV, attVT, M1);
    cvt_perm_kernel<<<256, 256>>>(attL, attLT, M2);
    tf32gemm_kernel<<<dim3(6, M1 / 128, 1), 128, GEMM_SMEM>>>(attVT, WuvT, bu_v, out, M1, 1.0f, 0);
    tf32gemm_kernel<<<dim3(6, M2 / 128, 1), 128, GEMM_SMEM>>>(attLT, WulT, bu_l, out + SF, M2, 1.0f, 0);
}

// round 10
// speedup vs baseline: 1.1575x; 1.1575x over previous
#include <cuda_runtime.h>
#include <cuda_bf16.h>
#include <math_constants.h>
#include <cstdint>

#define BB   16
#define T1C  512
#define T2C  64
#define DC   768
#define HC   12
#define EC   64
#define TKC  576
#define SCALE_P 0.3535533905932738f

// ---------------- scratch ----------------
__device__ float    g_projF[6ULL * BB * T1C * DC];   // tf32-bit floats
__device__ float    g_projI[6ULL * BB * T2C * DC];
__device__ float    g_attV [(size_t)BB * T1C * DC];  // plain fp32
__device__ float    g_attL [(size_t)BB * T2C * DC];
__device__ float    g_maskF[BB * TKC];
__device__ unsigned g_featsT[(size_t)BB * T1C * DC]; // tf32 bits, k-pair permuted
__device__ unsigned g_inpsT [(size_t)BB * T2C * DC];
__device__ unsigned g_attVT [(size_t)BB * T1C * DC];
__device__ unsigned g_attLT [(size_t)BB * T2C * DC];
__device__ unsigned g_WfT[6ULL * DC * DC];           // [z][n][k] tf32 bits, permuted
__device__ unsigned g_WiT[6ULL * DC * DC];
__device__ unsigned g_WuvT[(size_t)DC * DC];
__device__ unsigned g_WulT[(size_t)DC * DC];

__device__ __forceinline__ unsigned f2tf32(float x)
{ unsigned u; asm("cvt.rna.tf32.f32 %0, %1;" : "=r"(u) : "f"(x)); return u; }

#define MMA_TF32(d, a0, a1, a2, a3, b0, b1)                                   \
    asm volatile("mma.sync.aligned.m16n8k8.row.col.f32.tf32.tf32.f32 "        \
                 "{%0,%1,%2,%3}, {%4,%5,%6,%7}, {%8,%9}, {%0,%1,%2,%3};\n"    \
                 : "+f"(d[0]), "+f"(d[1]), "+f"(d[2]), "+f"(d[3])             \
                 : "r"(a0), "r"(a1), "r"(a2), "r"(a3), "r"(b0), "r"(b1))

__device__ __forceinline__ void cp16(void* dst, const void* src)
{
    unsigned sa = (unsigned)__cvta_generic_to_shared(dst);
    asm volatile("cp.async.ca.shared.global [%0], [%1], 16;" :: "r"(sa), "l"(src));
}
#define CP_COMMIT() asm volatile("cp.async.commit_group;")
template <int N>
__device__ __forceinline__ void cp_wait() { asm volatile("cp.async.wait_group %0;" :: "n"(N)); }

// ---------------- mask prep ----------------
__global__ void mask_prep_kernel(const unsigned* __restrict__ raw, float* __restrict__ mf)
{
    __shared__ int flags[2];
    int tid = threadIdx.x;
    if (tid < 2) flags[tid] = 0;
    __syncthreads();
    int notInt = 0, notU8 = 0;
    const int nWords = (BB * TKC) / 4;
    for (int i = tid; i < nWords; i += blockDim.x) {
        unsigned w = raw[i];
        if (w > 1u) notInt = 1;
        if (w & 0xFEFEFEFEu) notU8 = 1;
    }
    if (notInt) atomicOr(&flags[0], 1);
    if (notU8)  atomicOr(&flags[1], 1);
    __syncthreads();
    int mode = !flags[0] ? 0 : (!flags[1] ? 1 : 2);
    for (int i = tid; i < BB * TKC; i += blockDim.x) {
        float v;
        if (mode == 0)      v = ((const int*)raw)[i] ? 1.f : 0.f;
        else if (mode == 1) v = ((const unsigned char*)raw)[i] ? 1.f : 0.f;
        else                v = (((const float*)raw)[i] != 0.f) ? 1.f : 0.f;
        mf[i] = v;
    }
}

// ---------------- fp32 -> tf32 bits with k-pair permutation ----------------
// Each 8-k group reordered to [k0,k4,k1,k5,k2,k6,k3,k7]: a uint2 load at
// position 2*tg yields the (k=tg, k=tg+4) tf32 fragment pair.
__global__ void cvt_perm_kernel(const float* __restrict__ src, unsigned* __restrict__ dst, int M)
{
    int total = M * 96;
    for (int i = blockIdx.x * blockDim.x + threadIdx.x; i < total; i += gridDim.x * blockDim.x) {
        int m = i / 96, kq = i % 96;
        const float* s = src + (size_t)m * DC + kq * 8;
        float4 v0 = *(const float4*)s, v1 = *(const float4*)(s + 4);
        uint4 u0, u1;
        u0.x = f2tf32(v0.x); u0.y = f2tf32(v1.x); u0.z = f2tf32(v0.y); u0.w = f2tf32(v1.y);
        u1.x = f2tf32(v0.z); u1.y = f2tf32(v1.z); u1.z = f2tf32(v0.w); u1.w = f2tf32(v1.w);
        uint4* d = (uint4*)(dst + (size_t)m * DC + kq * 8);
        d[0] = u0; d[1] = u1;
    }
}

// ---------------- W[z][k][n] -> WT[z][n][k] tf32 bits, k-pair permuted ----------------
__global__ void wtrans_perm_kernel(const float* __restrict__ W, unsigned* __restrict__ WT)
{
    __shared__ float tile[64][65];
    int tid = threadIdx.x;
    int n0 = blockIdx.x * 64, k0 = blockIdx.y * 64;
    const float* Wz = W + (size_t)blockIdx.z * DC * DC;
    unsigned* Dz = WT + (size_t)blockIdx.z * DC * DC;

    for (int i = tid; i < 4096; i += 256) {
        int r = i >> 6, c = i & 63;
        tile[r][c] = Wz[(size_t)(k0 + r) * DC + n0 + c];
    }
    __syncthreads();
#pragma unroll
    for (int it = 0; it < 2; it++) {
        int idx = tid + it * 256;
        int n = idx >> 3, kq = idx & 7;
        float x[8];
#pragma unroll
        for (int j = 0; j < 8; j++) x[j] = tile[kq * 8 + j][n];
        uint4 u0, u1;
        u0.x = f2tf32(x[0]); u0.y = f2tf32(x[4]); u0.z = f2tf32(x[1]); u0.w = f2tf32(x[5]);
        u1.x = f2tf32(x[2]); u1.y = f2tf32(x[6]); u1.z = f2tf32(x[3]); u1.w = f2tf32(x[7]);
        uint4* d = (uint4*)(Dz + (size_t)(n0 + n) * DC + k0 + kq * 8);
        d[0] = u0; d[1] = u1;
    }
}

// ---------------- tf32 GEMM: R4 geometry + permuted uint2 fragment loads ----------------
// 256 threads / 8 warps, CTA tile 128x128, warp tile 64x32, chunk K=32, 2-stage.
// Both A and B in smem as [row][32 k-words permuted], PAD=40.
#define PAD 40
#define STG_WORDS (256 * PAD)            // A(128 rows) + B(128 rows) per stage
#define GEMM_SMEM (2 * STG_WORDS * 4)    // 81920 B

__global__ __launch_bounds__(256, 2) void tf32gemm_kernel(
    const unsigned* __restrict__ A, const unsigned* __restrict__ Bt,
    const float* __restrict__ bias, float* __restrict__ C,
    int M, float scale, int outTf32)
{
    extern __shared__ unsigned sh[];
    const int tid  = threadIdx.x;
    const int wid  = tid >> 5;
    const int lane = tid & 31;
    const int g    = lane >> 2;
    const int tg   = lane & 3;
    const int warpM = (wid & 1) * 64;
    const int warpN = (wid >> 1) * 32;

    const size_t z = blockIdx.z;
    Bt   += z * (size_t)DC * DC;
    bias += z * (size_t)DC;
    C    += z * (size_t)M * DC;

    const int rowBase = blockIdx.y * 128;
    const int colBase = blockIdx.x * 128;

    const int frow = tid >> 1;            // 0..127
    const int fhalf = (tid & 1) * 16;     // word offset within 32-word chunk

    const unsigned* Ag = A  + (size_t)(rowBase + frow) * DC + fhalf;
    const unsigned* Bg = Bt + (size_t)(colBase + frow) * DC + fhalf;

    float acc[4][4][4];
#pragma unroll
    for (int mt = 0; mt < 4; mt++)
#pragma unroll
        for (int nt = 0; nt < 4; nt++)
#pragma unroll
            for (int r = 0; r < 4; r++) acc[mt][nt][r] = 0.f;

    auto fill = [&](int b, int c) {
        unsigned* As = sh + b * STG_WORDS + frow * PAD + fhalf;
        unsigned* Bs = sh + b * STG_WORDS + 128 * PAD + frow * PAD + fhalf;
        const unsigned* As_g = Ag + c * 32;
        const unsigned* Bs_g = Bg + c * 32;
#pragma unroll
        for (int j = 0; j < 4; j++) cp16(As + j * 4, As_g + j * 4);
#pragma unroll
        for (int j = 0; j < 4; j++) cp16(Bs + j * 4, Bs_g + j * 4);
    };

    const int NC = DC / 32;   // 24
    fill(0, 0); CP_COMMIT();

    int buf = 0;
    for (int c = 0; c < NC; c++) {
        if (c + 1 < NC) { fill(buf ^ 1, c + 1); CP_COMMIT(); cp_wait<1>(); }
        else            { cp_wait<0>(); }
        __syncthreads();

        const unsigned* Ab = sh + buf * STG_WORDS;
        const unsigned* Bb = Ab + 128 * PAD;
#pragma unroll
        for (int ks = 0; ks < 32; ks += 8) {
            uint2 av[4][2];
#pragma unroll
            for (int mt = 0; mt < 4; mt++) {
                int r0 = warpM + mt * 16 + g;
                av[mt][0] = *(const uint2*)&Ab[r0 * PAD + ks + 2 * tg];
                av[mt][1] = *(const uint2*)&Ab[(r0 + 8) * PAD + ks + 2 * tg];
            }
            uint2 bv[4];
#pragma unroll
            for (int nt = 0; nt < 4; nt++)
                bv[nt] = *(const uint2*)&Bb[(warpN + nt * 8 + g) * PAD + ks + 2 * tg];
#pragma unroll
            for (int mt = 0; mt < 4; mt++)
#pragma unroll
                for (int nt = 0; nt < 4; nt++)
                    MMA_TF32(acc[mt][nt], av[mt][0].x, av[mt][1].x, av[mt][0].y, av[mt][1].y,
                             bv[nt].x, bv[nt].y);
        }
        __syncthreads();
        buf ^= 1;
    }

    // epilogue
#pragma unroll
    for (int mt = 0; mt < 4; mt++) {
        int row0 = rowBase + warpM + mt * 16 + g;
#pragma unroll
        for (int nt = 0; nt < 4; nt++) {
            int col = colBase + warpN + nt * 8 + 2 * tg;
            float b0 = bias[col], b1 = bias[col + 1];
            float v0 = (acc[mt][nt][0] + b0) * scale;
            float v1 = (acc[mt][nt][1] + b1) * scale;
            float v2 = (acc[mt][nt][2] + b0) * scale;
            float v3 = (acc[mt][nt][3] + b1) * scale;
            if (outTf32) {
                v0 = __uint_as_float(f2tf32(v0));
                v1 = __uint_as_float(f2tf32(v1));
                v2 = __uint_as_float(f2tf32(v2));
                v3 = __uint_as_float(f2tf32(v3));
            }
            *(float2*)(C + (size_t)row0 * DC + col)       = make_float2(v0, v1);
            *(float2*)(C + (size_t)(row0 + 8) * DC + col) = make_float2(v2, v3);
        }
    }
}

// ---------------- mma-based flash attention (tf32 in, fp32 out) ----------------
#define APAD 68
#define VPAD 72

__global__ __launch_bounds__(128) void attn_mma_kernel(
    const float* __restrict__ Qa, const float* __restrict__ Qb,
    const float* __restrict__ Kf, const float* __restrict__ Ki,
    const float* __restrict__ Vf, const float* __restrict__ Vi,
    const float* __restrict__ maskF, float* __restrict__ Out, int Tq)
{
    extern __shared__ unsigned smu[];
    unsigned* Qs = smu;
    unsigned* Ks = Qs + 64 * APAD;
    unsigned* Vs = Ks + 64 * APAD;
    unsigned* Ps = Vs + 64 * VPAD;
    float*    Ms = (float*)(Ps + 64 * APAD);

    const int tid = threadIdx.x;
    const int wid = tid >> 5;
    const int g = (tid & 31) >> 2;
    const int tg = tid & 3;
    const int wr = wid * 16;

    const int qt = blockIdx.x, h = blockIdx.y, b = blockIdx.z;
    const int qBase = qt * 64;

    const float* Qa_p = Qa + ((size_t)b * Tq + qBase) * DC + h * EC;
    const float* Qb_p = Qb + ((size_t)b * Tq + qBase) * DC + h * EC;
    const float* Kf_p = Kf + (size_t)b * T1C * DC + h * EC;
    const float* Ki_p = Ki + (size_t)b * T2C * DC + h * EC;
    const float* Vf_p = Vf + (size_t)b * T1C * DC + h * EC;
    const float* Vi_p = Vi + (size_t)b * T2C * DC + h * EC;

    for (int i = tid; i < TKC; i += 128) Ms[i] = maskF[b * TKC + i];

    for (int i = tid; i < 64 * 16; i += 128) {
        int r = i >> 4, c = (i & 15) << 2;
        *(uint4*)&Qs[r * APAD + c] = *(const uint4*)(Qa_p + (size_t)r * DC + c);
    }

    float o[8][4];
#pragma unroll
    for (int et = 0; et < 8; et++)
#pragma unroll
        for (int r = 0; r < 4; r++) o[et][r] = 0.f;
    float mx0 = -CUDART_INF_F, mx1 = -CUDART_INF_F, l0 = 0.f, l1 = 0.f;

    for (int t = 0; t < 9; t++) {
        const float *Kp, *Vp;
        int keyBase;
        if (t < 8) { Kp = Kf_p + (size_t)t * 64 * DC; Vp = Vf_p + (size_t)t * 64 * DC; keyBase = t * 64; }
        else       { Kp = Ki_p;                       Vp = Vi_p;                       keyBase = T1C; }

        __syncthreads();
        if (t == 8) {
            for (int i = tid; i < 64 * 16; i += 128) {
                int r = i >> 4, c = (i & 15) << 2;
                *(uint4*)&Qs[r * APAD + c] = *(const uint4*)(Qb_p + (size_t)r * DC + c);
            }
        }
        for (int i = tid; i < 64 * 16; i += 128) {
            int r = i >> 4, c = (i & 15) << 2;
            *(uint4*)&Ks[r * APAD + c] = *(const uint4*)(Kp + (size_t)r * DC + c);
            *(uint4*)&Vs[r * VPAD + c] = *(const uint4*)(Vp + (size_t)r * DC + c);
        }
        __syncthreads();

        float s[8][4];
#pragma unroll
        for (int nt = 0; nt < 8; nt++)
#pragma unroll
            for (int r = 0; r < 4; r++) s[nt][r] = 0.f;

#pragma unroll
        for (int ks = 0; ks < 64; ks += 8) {
            unsigned a0 = Qs[(wr + g) * APAD + ks + tg];
            unsigned a1 = Qs[(wr + g + 8) * APAD + ks + tg];
            unsigned a2 = Qs[(wr + g) * APAD + ks + tg + 4];
            unsigned a3 = Qs[(wr + g + 8) * APAD + ks + tg + 4];
#pragma unroll
            for (int nt = 0; nt < 8; nt++) {
                unsigned b0 = Ks[(nt * 8 + g) * APAD + ks + tg];
                unsigned b1 = Ks[(nt * 8 + g) * APAD + ks + tg + 4];
                MMA_TF32(s[nt], a0, a1, a2, a3, b0, b1);
            }
        }

        float tm0 = -CUDART_INF_F, tm1 = -CUDART_INF_F;
#pragma unroll
        for (int nt = 0; nt < 8; nt++) {
            float mk0 = Ms[keyBase + nt * 8 + 2 * tg];
            float mk1 = Ms[keyBase + nt * 8 + 2 * tg + 1];
            if (mk0 != 0.f) { s[nt][0] = -1e9f; s[nt][2] = -1e9f; }
            if (mk1 != 0.f) { s[nt][1] = -1e9f; s[nt][3] = -1e9f; }
            tm0 = fmaxf(tm0, fmaxf(s[nt][0], s[nt][1]));
            tm1 = fmaxf(tm1, fmaxf(s[nt][2], s[nt][3]));
        }
        tm0 = fmaxf(tm0, __shfl_xor_sync(0xffffffffu, tm0, 1));
        tm0 = fmaxf(tm0, __shfl_xor_sync(0xffffffffu, tm0, 2));
        tm1 = fmaxf(tm1, __shfl_xor_sync(0xffffffffu, tm1, 1));
        tm1 = fmaxf(tm1, __shfl_xor_sync(0xffffffffu, tm1, 2));

        float mn0 = fmaxf(mx0, tm0), mn1 = fmaxf(mx1, tm1);
        float sc0 = __expf(mx0 - mn0), sc1 = __expf(mx1 - mn1);
        mx0 = mn0; mx1 = mn1;

        float rs0 = 0.f, rs1 = 0.f;
#pragma unroll
        for (int nt = 0; nt < 8; nt++) {
            s[nt][0] = __expf(s[nt][0] - mn0); rs0 += s[nt][0];
            s[nt][1] = __expf(s[nt][1] - mn0); rs0 += s[nt][1];
            s[nt][2] = __expf(s[nt][2] - mn1); rs1 += s[nt][2];
            s[nt][3] = __expf(s[nt][3] - mn1); rs1 += s[nt][3];
        }
        rs0 += __shfl_xor_sync(0xffffffffu, rs0, 1);
        rs0 += __shfl_xor_sync(0xffffffffu, rs0, 2);
        rs1 += __shfl_xor_sync(0xffffffffu, rs1, 1);
        rs1 += __shfl_xor_sync(0xffffffffu, rs1, 2);
        l0 = l0 * sc0 + rs0;
        l1 = l1 * sc1 + rs1;
#pragma unroll
        for (int et = 0; et < 8; et++) {
            o[et][0] *= sc0; o[et][1] *= sc0;
            o[et][2] *= sc1; o[et][3] *= sc1;
        }

#pragma unroll
        for (int nt = 0; nt < 8; nt++) {
            *(uint2*)&Ps[(wr + g) * APAD + nt * 8 + 2 * tg]     = make_uint2(f2tf32(s[nt][0]), f2tf32(s[nt][1]));
            *(uint2*)&Ps[(wr + g + 8) * APAD + nt * 8 + 2 * tg] = make_uint2(f2tf32(s[nt][2]), f2tf32(s[nt][3]));
        }
        __syncwarp();

#pragma unroll
        for (int ks = 0; ks < 64; ks += 8) {
            unsigned a0 = Ps[(wr + g) * APAD + ks + tg];
            unsigned a1 = Ps[(wr + g + 8) * APAD + ks + tg];
            unsigned a2 = Ps[(wr + g) * APAD + ks + tg + 4];
            unsigned a3 = Ps[(wr + g + 8) * APAD + ks + tg + 4];
#pragma unroll
            for (int et = 0; et < 8; et++) {
                unsigned b0 = Vs[(ks + tg) * VPAD + et * 8 + g];
                unsigned b1 = Vs[(ks + tg + 4) * VPAD + et * 8 + g];
                MMA_TF32(o[et], a0, a1, a2, a3, b0, b1);
            }
        }
    }

    float inv0 = 1.f / l0, inv1 = 1.f / l1;
    int r0 = qBase + wr + g;
#pragma unroll
    for (int et = 0; et < 8; et++) {
        int col = h * EC + et * 8 + 2 * tg;
        *(float2*)(Out + ((size_t)b * Tq + r0) * DC + col)     = make_float2(o[et][0] * inv0, o[et][1] * inv0);
        *(float2*)(Out + ((size_t)b * Tq + r0 + 8) * DC + col) = make_float2(o[et][2] * inv1, o[et][3] * inv1);
    }
}

// ---------------- launch ----------------
extern "C" void kernel_launch(void* const* d_in, const int* in_sizes, int n_in,
                              void* d_out, int out_size)
{
    const float* feats = (const float*)d_in[0];
    const float* inps  = (const float*)d_in[1];
    const void*  amask = d_in[2];
    const float* W_f   = (const float*)d_in[3];
    const float* b_f   = (const float*)d_in[4];
    const float* W_i   = (const float*)d_in[5];
    const float* b_i   = (const float*)d_in[6];
    const float* Wu_v  = (const float*)d_in[7];
    const float* bu_v  = (const float*)d_in[8];
    const float* Wu_l  = (const float*)d_in[9];
    const float* bu_l  = (const float*)d_in[10];
    float* out = (float*)d_out;

    float *projF, *projI, *attV, *attL, *maskF;
    unsigned *featsT, *inpsT, *attVT, *attLT, *WfT, *WiT, *WuvT, *WulT;
    cudaGetSymbolAddress((void**)&projF, g_projF);
    cudaGetSymbolAddress((void**)&projI, g_projI);
    cudaGetSymbolAddress((void**)&attV,  g_attV);
    cudaGetSymbolAddress((void**)&attL,  g_attL);
    cudaGetSymbolAddress((void**)&maskF, g_maskF);
    cudaGetSymbolAddress((void**)&featsT, g_featsT);
    cudaGetSymbolAddress((void**)&inpsT,  g_inpsT);
    cudaGetSymbolAddress((void**)&attVT,  g_attVT);
    cudaGetSymbolAddress((void**)&attLT,  g_attLT);
    cudaGetSymbolAddress((void**)&WfT,  g_WfT);
    cudaGetSymbolAddress((void**)&WiT,  g_WiT);
    cudaGetSymbolAddress((void**)&WuvT, g_WuvT);
    cudaGetSymbolAddress((void**)&WulT, g_WulT);

    const size_t SF = (size_t)BB * T1C * DC;
    const size_t SI = (size_t)BB * T2C * DC;
    const int M1 = BB * T1C, M2 = BB * T2C;

    const int attnSmem = (3 * 64 * APAD + 64 * VPAD + TKC) * (int)sizeof(unsigned);
    cudaFuncSetAttribute(tf32gemm_kernel, cudaFuncAttributeMaxDynamicSharedMemorySize, GEMM_SMEM);
    cudaFuncSetAttribute(attn_mma_kernel, cudaFuncAttributeMaxDynamicSharedMemorySize, attnSmem);

    // 1) prep: mask + permuted tf32 operands
    mask_prep_kernel<<<1, 256>>>((const unsigned*)amask, maskF);
    cvt_perm_kernel<<<1024, 256>>>(feats, featsT, M1);
    cvt_perm_kernel<<<256, 256>>>(inps, inpsT, M2);
    wtrans_perm_kernel<<<dim3(12, 12, 6), 256>>>(W_f, WfT);
    wtrans_perm_kernel<<<dim3(12, 12, 6), 256>>>(W_i, WiT);
    wtrans_perm_kernel<<<dim3(12, 12, 1), 256>>>(Wu_v, WuvT);
    wtrans_perm_kernel<<<dim3(12, 12, 1), 256>>>(Wu_l, WulT);

    // 2) projections (tf32-rounded out for attention)
    tf32gemm_kernel<<<dim3(6, M1 / 128, 6), 256, GEMM_SMEM>>>(featsT, WfT, b_f, projF, M1, SCALE_P, 1);
    tf32gemm_kernel<<<dim3(6, M2 / 128, 6), 256, GEMM_SMEM>>>(inpsT, WiT, b_i, projI, M2, SCALE_P, 1);

    // feats stack: [k_vv, q_vv, v_vv, q_lv, k_vl, v_vl]
    // inps  stack: [k_lv, v_lv, q_vl, q_ll, k_ll, v_ll]

    // 3) attention (fp32 out)
    attn_mma_kernel<<<dim3(T1C / 64, HC, BB), 128, attnSmem>>>(
        projF + 1 * SF, projF + 3 * SF,
        projF + 0 * SF, projI + 0 * SI,
        projF + 2 * SF, projI + 1 * SI,
        maskF, attV, T1C);
    attn_mma_kernel<<<dim3(T2C / 64, HC, BB), 128, attnSmem>>>(
        projI + 2 * SI, projI + 3 * SI,
        projF + 4 * SF, projI + 4 * SI,
        projF + 5 * SF, projI + 5 * SI,
        maskF, attL, T2C);

    // 4) permute attention outputs, then output projections into d_out
    cvt_perm_kernel<<<1024, 256>>>(attV, attVT, M1);
    cvt_perm_kernel<<<256, 256>>>(attL, attLT, M2);
    tf32gemm_kernel<<<dim3(6, M1 / 128, 1), 256, GEMM_SMEM>>>(attVT, WuvT, bu_v, out, M1, 1.0f, 0);
    tf32gemm_kernel<<<dim3(6, M2 / 128, 1), 256, GEMM_SMEM>>>(attLT, WulT, bu_l, out + SF, M2, 1.0f, 0);
}

// round 11
// speedup vs baseline: 1.3662x; 1.1803x over previous
#include <cuda_runtime.h>
#include <cuda_bf16.h>
#include <math_constants.h>
#include <cstdint>

#define BB   16
#define T1C  512
#define T2C  64
#define DC   768
#define HC   12
#define EC   64
#define TKC  576
#define SCALE_P 0.3535533905932738f

// ---------------- scratch ----------------
__device__ float    g_projF[6ULL * BB * T1C * DC];   // tf32-bit floats
__device__ float    g_projI[6ULL * BB * T2C * DC];
__device__ float    g_attV [(size_t)BB * T1C * DC];  // plain fp32
__device__ float    g_attL [(size_t)BB * T2C * DC];
__device__ float    g_maskF[BB * TKC];
__device__ unsigned g_featsT[(size_t)BB * T1C * DC]; // tf32 bits, k-pair permuted
__device__ unsigned g_inpsT [(size_t)BB * T2C * DC];
__device__ unsigned g_attVT [(size_t)BB * T1C * DC];
__device__ unsigned g_attLT [(size_t)BB * T2C * DC];
__device__ unsigned g_WfT[6ULL * DC * DC];           // [z][n][k] tf32 bits, permuted
__device__ unsigned g_WiT[6ULL * DC * DC];
__device__ unsigned g_WuvT[(size_t)DC * DC];
__device__ unsigned g_WulT[(size_t)DC * DC];

__device__ __forceinline__ unsigned f2tf32(float x)
{ unsigned u; asm("cvt.rna.tf32.f32 %0, %1;" : "=r"(u) : "f"(x)); return u; }

#define MMA_TF32(d, a0, a1, a2, a3, b0, b1)                                   \
    asm volatile("mma.sync.aligned.m16n8k8.row.col.f32.tf32.tf32.f32 "        \
                 "{%0,%1,%2,%3}, {%4,%5,%6,%7}, {%8,%9}, {%0,%1,%2,%3};\n"    \
                 : "+f"(d[0]), "+f"(d[1]), "+f"(d[2]), "+f"(d[3])             \
                 : "r"(a0), "r"(a1), "r"(a2), "r"(a3), "r"(b0), "r"(b1))

__device__ __forceinline__ void cp16(void* dst, const void* src)
{
    unsigned sa = (unsigned)__cvta_generic_to_shared(dst);
    asm volatile("cp.async.ca.shared.global [%0], [%1], 16;" :: "r"(sa), "l"(src));
}
#define CP_COMMIT() asm volatile("cp.async.commit_group;")
template <int N>
__device__ __forceinline__ void cp_wait() { asm volatile("cp.async.wait_group %0;" :: "n"(N)); }

// ---------------- mask prep ----------------
__global__ void mask_prep_kernel(const unsigned* __restrict__ raw, float* __restrict__ mf)
{
    __shared__ int flags[2];
    int tid = threadIdx.x;
    if (tid < 2) flags[tid] = 0;
    __syncthreads();
    int notInt = 0, notU8 = 0;
    const int nWords = (BB * TKC) / 4;
    for (int i = tid; i < nWords; i += blockDim.x) {
        unsigned w = raw[i];
        if (w > 1u) notInt = 1;
        if (w & 0xFEFEFEFEu) notU8 = 1;
    }
    if (notInt) atomicOr(&flags[0], 1);
    if (notU8)  atomicOr(&flags[1], 1);
    __syncthreads();
    int mode = !flags[0] ? 0 : (!flags[1] ? 1 : 2);
    for (int i = tid; i < BB * TKC; i += blockDim.x) {
        float v;
        if (mode == 0)      v = ((const int*)raw)[i] ? 1.f : 0.f;
        else if (mode == 1) v = ((const unsigned char*)raw)[i] ? 1.f : 0.f;
        else                v = (((const float*)raw)[i] != 0.f) ? 1.f : 0.f;
        mf[i] = v;
    }
}

// ---------------- fp32 -> tf32 bits, k-pair permuted; two regions per launch ----------------
__global__ void cvt_perm2_kernel(const float* __restrict__ s0, unsigned* __restrict__ d0, int n0,
                                 const float* __restrict__ s1, unsigned* __restrict__ d1, int n1)
{
    const float* src; unsigned* dst; int total;
    if (blockIdx.y == 0) { src = s0; dst = d0; total = n0; }
    else                 { src = s1; dst = d1; total = n1; }
    for (int i = blockIdx.x * blockDim.x + threadIdx.x; i < total; i += gridDim.x * blockDim.x) {
        int m = i / 96, kq = i % 96;
        const float* s = src + (size_t)m * DC + kq * 8;
        float4 v0 = *(const float4*)s, v1 = *(const float4*)(s + 4);
        uint4 u0, u1;
        u0.x = f2tf32(v0.x); u0.y = f2tf32(v1.x); u0.z = f2tf32(v0.y); u0.w = f2tf32(v1.y);
        u1.x = f2tf32(v0.z); u1.y = f2tf32(v1.z); u1.z = f2tf32(v0.w); u1.w = f2tf32(v1.w);
        uint4* d = (uint4*)(dst + (size_t)m * DC + kq * 8);
        d[0] = u0; d[1] = u1;
    }
}

// ---------------- all weights: W[k][n] -> WT[n][k] tf32 permuted, one launch ----------------
__global__ void wtrans_all_kernel(const float* __restrict__ Wf, const float* __restrict__ Wi,
                                  const float* __restrict__ Wuv, const float* __restrict__ Wul,
                                  unsigned* __restrict__ WfT, unsigned* __restrict__ WiT,
                                  unsigned* __restrict__ WuvT, unsigned* __restrict__ WulT)
{
    __shared__ float tile[64][65];
    int tid = threadIdx.x;
    int n0 = blockIdx.x * 64, k0 = blockIdx.y * 64;
    int zz = blockIdx.z;
    const float* Wz; unsigned* Dz;
    if (zz < 6)       { Wz = Wf  + (size_t)zz * DC * DC;       Dz = WfT + (size_t)zz * DC * DC; }
    else if (zz < 12) { Wz = Wi  + (size_t)(zz - 6) * DC * DC; Dz = WiT + (size_t)(zz - 6) * DC * DC; }
    else if (zz == 12){ Wz = Wuv;                              Dz = WuvT; }
    else              { Wz = Wul;                              Dz = WulT; }

    for (int i = tid; i < 4096; i += 256) {
        int r = i >> 6, c = i & 63;
        tile[r][c] = Wz[(size_t)(k0 + r) * DC + n0 + c];
    }
    __syncthreads();
#pragma unroll
    for (int it = 0; it < 2; it++) {
        int idx = tid + it * 256;
        int n = idx >> 3, kq = idx & 7;
        float x[8];
#pragma unroll
        for (int j = 0; j < 8; j++) x[j] = tile[kq * 8 + j][n];
        uint4 u0, u1;
        u0.x = f2tf32(x[0]); u0.y = f2tf32(x[4]); u0.z = f2tf32(x[1]); u0.w = f2tf32(x[5]);
        u1.x = f2tf32(x[2]); u1.y = f2tf32(x[6]); u1.z = f2tf32(x[3]); u1.w = f2tf32(x[7]);
        uint4* d = (uint4*)(Dz + (size_t)(n0 + n) * DC + k0 + kq * 8);
        d[0] = u0; d[1] = u1;
    }
}

// ---------------- tf32 GEMM: 512 threads, 32x32 warp tiles, y-split dual-problem ----------------
#define PAD 40
#define STG_WORDS (256 * PAD)            // A(128 rows) + B(128 rows) per stage
#define GEMM_SMEM (2 * STG_WORDS * 4)    // 81920 B

__global__ __launch_bounds__(512, 2) void tf32gemm_kernel(
    const unsigned* __restrict__ A0, const unsigned* __restrict__ B0,
    const float* __restrict__ bias0, float* __restrict__ C0, int M0,
    const unsigned* __restrict__ A1, const unsigned* __restrict__ B1,
    const float* __restrict__ bias1, float* __restrict__ C1, int M1r,
    int ySplit, float scale, int outTf32)
{
    extern __shared__ unsigned sh[];
    const int tid  = threadIdx.x;
    const int wid  = tid >> 5;
    const int lane = tid & 31;
    const int g    = lane >> 2;
    const int tg   = lane & 3;
    const int warpM = (wid & 3) * 32;
    const int warpN = (wid >> 2) * 32;

    int yy = blockIdx.y;
    const unsigned* A; const unsigned* Bt; const float* bias; float* C; int M;
    if (yy < ySplit) { A = A0; Bt = B0; bias = bias0; C = C0; M = M0; }
    else             { A = A1; Bt = B1; bias = bias1; C = C1; M = M1r; yy -= ySplit; }

    const size_t z = blockIdx.z;
    Bt   += z * (size_t)DC * DC;
    bias += z * (size_t)DC;
    C    += z * (size_t)M * DC;

    const int rowBase = yy * 128;
    const int colBase = blockIdx.x * 128;

    const int frow = tid >> 2;            // 0..127
    const int fq   = (tid & 3) * 8;       // word offset 0,8,16,24

    const unsigned* Ag = A  + (size_t)(rowBase + frow) * DC + fq;
    const unsigned* Bg = Bt + (size_t)(colBase + frow) * DC + fq;

    float acc[2][4][4];
#pragma unroll
    for (int mt = 0; mt < 2; mt++)
#pragma unroll
        for (int nt = 0; nt < 4; nt++)
#pragma unroll
            for (int r = 0; r < 4; r++) acc[mt][nt][r] = 0.f;

    auto fill = [&](int b, int c) {
        unsigned* As = sh + b * STG_WORDS + frow * PAD + fq;
        unsigned* Bs = sh + b * STG_WORDS + 128 * PAD + frow * PAD + fq;
        const unsigned* As_g = Ag + c * 32;
        const unsigned* Bs_g = Bg + c * 32;
        cp16(As, As_g); cp16(As + 4, As_g + 4);
        cp16(Bs, Bs_g); cp16(Bs + 4, Bs_g + 4);
    };

    const int NC = DC / 32;   // 24
    fill(0, 0); CP_COMMIT();

    int buf = 0;
    for (int c = 0; c < NC; c++) {
        if (c + 1 < NC) { fill(buf ^ 1, c + 1); CP_COMMIT(); cp_wait<1>(); }
        else            { cp_wait<0>(); }
        __syncthreads();

        const unsigned* Ab = sh + buf * STG_WORDS;
        const unsigned* Bb = Ab + 128 * PAD;
#pragma unroll
        for (int ks = 0; ks < 32; ks += 8) {
            uint2 av[2][2];
#pragma unroll
            for (int mt = 0; mt < 2; mt++) {
                int r0 = warpM + mt * 16 + g;
                av[mt][0] = *(const uint2*)&Ab[r0 * PAD + ks + 2 * tg];
                av[mt][1] = *(const uint2*)&Ab[(r0 + 8) * PAD + ks + 2 * tg];
            }
            uint2 bv[4];
#pragma unroll
            for (int nt = 0; nt < 4; nt++)
                bv[nt] = *(const uint2*)&Bb[(warpN + nt * 8 + g) * PAD + ks + 2 * tg];
#pragma unroll
            for (int mt = 0; mt < 2; mt++)
#pragma unroll
                for (int nt = 0; nt < 4; nt++)
                    MMA_TF32(acc[mt][nt], av[mt][0].x, av[mt][1].x, av[mt][0].y, av[mt][1].y,
                             bv[nt].x, bv[nt].y);
        }
        __syncthreads();
        buf ^= 1;
    }

    // epilogue
#pragma unroll
    for (int mt = 0; mt < 2; mt++) {
        int row0 = rowBase + warpM + mt * 16 + g;
#pragma unroll
        for (int nt = 0; nt < 4; nt++) {
            int col = colBase + warpN + nt * 8 + 2 * tg;
            float b0 = bias[col], b1 = bias[col + 1];
            float v0 = (acc[mt][nt][0] + b0) * scale;
            float v1 = (acc[mt][nt][1] + b1) * scale;
            float v2 = (acc[mt][nt][2] + b0) * scale;
            float v3 = (acc[mt][nt][3] + b1) * scale;
            if (outTf32) {
                v0 = __uint_as_float(f2tf32(v0));
                v1 = __uint_as_float(f2tf32(v1));
                v2 = __uint_as_float(f2tf32(v2));
                v3 = __uint_as_float(f2tf32(v3));
            }
            *(float2*)(C + (size_t)row0 * DC + col)       = make_float2(v0, v1);
            *(float2*)(C + (size_t)(row0 + 8) * DC + col) = make_float2(v2, v3);
        }
    }
}

// ---------------- mma-based flash attention, both streams in one launch ----------------
#define APAD 68
#define VPAD 72

__global__ __launch_bounds__(128) void attn_mma_kernel(
    const float* __restrict__ Qa0, const float* __restrict__ Qb0,
    const float* __restrict__ Kf0, const float* __restrict__ Ki0,
    const float* __restrict__ Vf0, const float* __restrict__ Vi0,
    float* __restrict__ Out0,
    const float* __restrict__ Qa1, const float* __restrict__ Qb1,
    const float* __restrict__ Kf1, const float* __restrict__ Ki1,
    const float* __restrict__ Vf1, const float* __restrict__ Vi1,
    float* __restrict__ Out1,
    const float* __restrict__ maskF, int xSplit)
{
    extern __shared__ unsigned smu[];
    unsigned* Qs = smu;
    unsigned* Ks = Qs + 64 * APAD;
    unsigned* Vs = Ks + 64 * APAD;
    unsigned* Ps = Vs + 64 * VPAD;
    float*    Ms = (float*)(Ps + 64 * APAD);

    const int tid = threadIdx.x;
    const int wid = tid >> 5;
    const int g = (tid & 31) >> 2;
    const int tg = tid & 3;
    const int wr = wid * 16;

    const int h = blockIdx.y, b = blockIdx.z;
    int qt = blockIdx.x;
    const float *Qa, *Qb, *Kf, *Ki, *Vf, *Vi; float* Out; int Tq;
    if (qt < xSplit) { Qa = Qa0; Qb = Qb0; Kf = Kf0; Ki = Ki0; Vf = Vf0; Vi = Vi0; Out = Out0; Tq = T1C; }
    else             { Qa = Qa1; Qb = Qb1; Kf = Kf1; Ki = Ki1; Vf = Vf1; Vi = Vi1; Out = Out1; Tq = T2C; qt -= xSplit; }
    const int qBase = qt * 64;

    const float* Qa_p = Qa + ((size_t)b * Tq + qBase) * DC + h * EC;
    const float* Qb_p = Qb + ((size_t)b * Tq + qBase) * DC + h * EC;
    const float* Kf_p = Kf + (size_t)b * T1C * DC + h * EC;
    const float* Ki_p = Ki + (size_t)b * T2C * DC + h * EC;
    const float* Vf_p = Vf + (size_t)b * T1C * DC + h * EC;
    const float* Vi_p = Vi + (size_t)b * T2C * DC + h * EC;

    for (int i = tid; i < TKC; i += 128) Ms[i] = maskF[b * TKC + i];

    for (int i = tid; i < 64 * 16; i += 128) {
        int r = i >> 4, c = (i & 15) << 2;
        *(uint4*)&Qs[r * APAD + c] = *(const uint4*)(Qa_p + (size_t)r * DC + c);
    }

    float o[8][4];
#pragma unroll
    for (int et = 0; et < 8; et++)
#pragma unroll
        for (int r = 0; r < 4; r++) o[et][r] = 0.f;
    float mx0 = -CUDART_INF_F, mx1 = -CUDART_INF_F, l0 = 0.f, l1 = 0.f;

    for (int t = 0; t < 9; t++) {
        const float *Kp, *Vp;
        int keyBase;
        if (t < 8) { Kp = Kf_p + (size_t)t * 64 * DC; Vp = Vf_p + (size_t)t * 64 * DC; keyBase = t * 64; }
        else       { Kp = Ki_p;                       Vp = Vi_p;                       keyBase = T1C; }

        __syncthreads();
        if (t == 8) {
            for (int i = tid; i < 64 * 16; i += 128) {
                int r = i >> 4, c = (i & 15) << 2;
                *(uint4*)&Qs[r * APAD + c] = *(const uint4*)(Qb_p + (size_t)r * DC + c);
            }
        }
        for (int i = tid; i < 64 * 16; i += 128) {
            int r = i >> 4, c = (i & 15) << 2;
            *(uint4*)&Ks[r * APAD + c] = *(const uint4*)(Kp + (size_t)r * DC + c);
            *(uint4*)&Vs[r * VPAD + c] = *(const uint4*)(Vp + (size_t)r * DC + c);
        }
        __syncthreads();

        float s[8][4];
#pragma unroll
        for (int nt = 0; nt < 8; nt++)
#pragma unroll
            for (int r = 0; r < 4; r++) s[nt][r] = 0.f;

#pragma unroll
        for (int ks = 0; ks < 64; ks += 8) {
            unsigned a0 = Qs[(wr + g) * APAD + ks + tg];
            unsigned a1 = Qs[(wr + g + 8) * APAD + ks + tg];
            unsigned a2 = Qs[(wr + g) * APAD + ks + tg + 4];
            unsigned a3 = Qs[(wr + g + 8) * APAD + ks + tg + 4];
#pragma unroll
            for (int nt = 0; nt < 8; nt++) {
                unsigned b0 = Ks[(nt * 8 + g) * APAD + ks + tg];
                unsigned b1 = Ks[(nt * 8 + g) * APAD + ks + tg + 4];
                MMA_TF32(s[nt], a0, a1, a2, a3, b0, b1);
            }
        }

        float tm0 = -CUDART_INF_F, tm1 = -CUDART_INF_F;
#pragma unroll
        for (int nt = 0; nt < 8; nt++) {
            float mk0 = Ms[keyBase + nt * 8 + 2 * tg];
            float mk1 = Ms[keyBase + nt * 8 + 2 * tg + 1];
            if (mk0 != 0.f) { s[nt][0] = -1e9f; s[nt][2] = -1e9f; }
            if (mk1 != 0.f) { s[nt][1] = -1e9f; s[nt][3] = -1e9f; }
            tm0 = fmaxf(tm0, fmaxf(s[nt][0], s[nt][1]));
            tm1 = fmaxf(tm1, fmaxf(s[nt][2], s[nt][3]));
        }
        tm0 = fmaxf(tm0, __shfl_xor_sync(0xffffffffu, tm0, 1));
        tm0 = fmaxf(tm0, __shfl_xor_sync(0xffffffffu, tm0, 2));
        tm1 = fmaxf(tm1, __shfl_xor_sync(0xffffffffu, tm1, 1));
        tm1 = fmaxf(tm1, __shfl_xor_sync(0xffffffffu, tm1, 2));

        float mn0 = fmaxf(mx0, tm0), mn1 = fmaxf(mx1, tm1);
        float sc0 = __expf(mx0 - mn0), sc1 = __expf(mx1 - mn1);
        mx0 = mn0; mx1 = mn1;

        float rs0 = 0.f, rs1 = 0.f;
#pragma unroll
        for (int nt = 0; nt < 8; nt++) {
            s[nt][0] = __expf(s[nt][0] - mn0); rs0 += s[nt][0];
            s[nt][1] = __expf(s[nt][1] - mn0); rs0 += s[nt][1];
            s[nt][2] = __expf(s[nt][2] - mn1); rs1 += s[nt][2];
            s[nt][3] = __expf(s[nt][3] - mn1); rs1 += s[nt][3];
        }
        rs0 += __shfl_xor_sync(0xffffffffu, rs0, 1);
        rs0 += __shfl_xor_sync(0xffffffffu, rs0, 2);
        rs1 += __shfl_xor_sync(0xffffffffu, rs1, 1);
        rs1 += __shfl_xor_sync(0xffffffffu, rs1, 2);
        l0 = l0 * sc0 + rs0;
        l1 = l1 * sc1 + rs1;
#pragma unroll
        for (int et = 0; et < 8; et++) {
            o[et][0] *= sc0; o[et][1] *= sc0;
            o[et][2] *= sc1; o[et][3] *= sc1;
        }

#pragma unroll
        for (int nt = 0; nt < 8; nt++) {
            *(uint2*)&Ps[(wr + g) * APAD + nt * 8 + 2 * tg]     = make_uint2(f2tf32(s[nt][0]), f2tf32(s[nt][1]));
            *(uint2*)&Ps[(wr + g + 8) * APAD + nt * 8 + 2 * tg] = make_uint2(f2tf32(s[nt][2]), f2tf32(s[nt][3]));
        }
        __syncwarp();

#pragma unroll
        for (int ks = 0; ks < 64; ks += 8) {
            unsigned a0 = Ps[(wr + g) * APAD + ks + tg];
            unsigned a1 = Ps[(wr + g + 8) * APAD + ks + tg];
            unsigned a2 = Ps[(wr + g) * APAD + ks + tg + 4];
            unsigned a3 = Ps[(wr + g + 8) * APAD + ks + tg + 4];
#pragma unroll
            for (int et = 0; et < 8; et++) {
                unsigned b0 = Vs[(ks + tg) * VPAD + et * 8 + g];
                unsigned b1 = Vs[(ks + tg + 4) * VPAD + et * 8 + g];
                MMA_TF32(o[et], a0, a1, a2, a3, b0, b1);
            }
        }
    }

    float inv0 = 1.f / l0, inv1 = 1.f / l1;
    int r0 = qBase + wr + g;
#pragma unroll
    for (int et = 0; et < 8; et++) {
        int col = h * EC + et * 8 + 2 * tg;
        *(float2*)(Out + ((size_t)b * Tq + r0) * DC + col)     = make_float2(o[et][0] * inv0, o[et][1] * inv0);
        *(float2*)(Out + ((size_t)b * Tq + r0 + 8) * DC + col) = make_float2(o[et][2] * inv1, o[et][3] * inv1);
    }
}

// ---------------- launch ----------------
extern "C" void kernel_launch(void* const* d_in, const int* in_sizes, int n_in,
                              void* d_out, int out_size)
{
    const float* feats = (const float*)d_in[0];
    const float* inps  = (const float*)d_in[1];
    const void*  amask = d_in[2];
    const float* W_f   = (const float*)d_in[3];
    const float* b_f   = (const float*)d_in[4];
    const float* W_i   = (const float*)d_in[5];
    const float* b_i   = (const float*)d_in[6];
    const float* Wu_v  = (const float*)d_in[7];
    const float* bu_v  = (const float*)d_in[8];
    const float* Wu_l  = (const float*)d_in[9];
    const float* bu_l  = (const float*)d_in[10];
    float* out = (float*)d_out;

    float *projF, *projI, *attV, *attL, *maskF;
    unsigned *featsT, *inpsT, *attVT, *attLT, *WfT, *WiT, *WuvT, *WulT;
    cudaGetSymbolAddress((void**)&projF, g_projF);
    cudaGetSymbolAddress((void**)&projI, g_projI);
    cudaGetSymbolAddress((void**)&attV,  g_attV);
    cudaGetSymbolAddress((void**)&attL,  g_attL);
    cudaGetSymbolAddress((void**)&maskF, g_maskF);
    cudaGetSymbolAddress((void**)&featsT, g_featsT);
    cudaGetSymbolAddress((void**)&inpsT,  g_inpsT);
    cudaGetSymbolAddress((void**)&attVT,  g_attVT);
    cudaGetSymbolAddress((void**)&attLT,  g_attLT);
    cudaGetSymbolAddress((void**)&WfT,  g_WfT);
    cudaGetSymbolAddress((void**)&WiT,  g_WiT);
    cudaGetSymbolAddress((void**)&WuvT, g_WuvT);
    cudaGetSymbolAddress((void**)&WulT, g_WulT);

    const size_t SF = (size_t)BB * T1C * DC;
    const size_t SI = (size_t)BB * T2C * DC;
    const int M1 = BB * T1C, M2 = BB * T2C;

    const int attnSmem = (3 * 64 * APAD + 64 * VPAD + TKC) * (int)sizeof(unsigned);
    cudaFuncSetAttribute(tf32gemm_kernel, cudaFuncAttributeMaxDynamicSharedMemorySize, GEMM_SMEM);
    cudaFuncSetAttribute(attn_mma_kernel, cudaFuncAttributeMaxDynamicSharedMemorySize, attnSmem);

    // 1) prep (3 launches)
    mask_prep_kernel<<<1, 256>>>((const unsigned*)amask, maskF);
    cvt_perm2_kernel<<<dim3(1024, 2), 256>>>(feats, featsT, M1 * 96, inps, inpsT, M2 * 96);
    wtrans_all_kernel<<<dim3(12, 12, 14), 256>>>(W_f, W_i, Wu_v, Wu_l, WfT, WiT, WuvT, WulT);

    // 2) both projection stacks in ONE launch (y-split 64|8), tf32-rounded out
    tf32gemm_kernel<<<dim3(6, 72, 6), 512, GEMM_SMEM>>>(
        featsT, WfT, b_f, projF, M1,
        inpsT,  WiT, b_i, projI, M2,
        64, SCALE_P, 1);

    // feats stack: [k_vv, q_vv, v_vv, q_lv, k_vl, v_vl]
    // inps  stack: [k_lv, v_lv, q_vl, q_ll, k_ll, v_ll]

    // 3) both attention streams in ONE launch (x-split 8|1), fp32 out
    attn_mma_kernel<<<dim3(9, HC, BB), 128, attnSmem>>>(
        projF + 1 * SF, projF + 3 * SF, projF + 0 * SF, projI + 0 * SI,
        projF + 2 * SF, projI + 1 * SI, attV,
        projI + 2 * SI, projI + 3 * SI, projF + 4 * SF, projI + 4 * SI,
        projF + 5 * SF, projI + 5 * SI, attL,
        maskF, 8);

    // 4) permute attention outputs (one launch), then both out-projections in ONE launch
    cvt_perm2_kernel<<<dim3(1024, 2), 256>>>(attV, attVT, M1 * 96, attL, attLT, M2 * 96);
    tf32gemm_kernel<<<dim3(6, 72, 1), 512, GEMM_SMEM>>>(
        attVT, WuvT, bu_v, out, M1,
        attLT, WulT, bu_l, out + SF, M2,
        64, 1.0f, 0);
}